// round 4
// baseline (speedup 1.0000x reference)
#include <cuda_runtime.h>
#include <cuda_bf16.h>
#include <stdint.h>
#include <math.h>

#define BATCH 4
#define SEQ   2048
#define HDIM  1024
#define EDIM  1024
#define MTOT  (BATCH * SEQ)          // 8192

typedef __nv_bfloat16 bf16;

// ---------------------------------------------------------------------------
// Scratch (device globals)
// ---------------------------------------------------------------------------
__device__ bf16  g_xh[(size_t)MTOT * HDIM],  g_xl[(size_t)MTOT * HDIM];     // 16MB ea
__device__ bf16  g_wh[(size_t)3 * EDIM * HDIM], g_wl[(size_t)3 * EDIM * HDIM]; // 6MB ea
__device__ bf16  g_qh[(size_t)MTOT * EDIM],  g_ql[(size_t)MTOT * EDIM];
__device__ bf16  g_kh[(size_t)MTOT * EDIM],  g_kl[(size_t)MTOT * EDIM];
__device__ bf16  g_vth[(size_t)EDIM * MTOT], g_vtl[(size_t)EDIM * MTOT];
__device__ float g_p [(size_t)BATCH * SEQ * SEQ];                           // 64MB
__device__ bf16  g_ph[(size_t)BATCH * SEQ * SEQ], g_pl[(size_t)BATCH * SEQ * SEQ];

// ---------------------------------------------------------------------------
// Tile geometry: K-chunk = 32 bf16 (64B payload), rows padded to 80B.
// ---------------------------------------------------------------------------
#define TROW     80
#define TILE_B   (128 * TROW)          // 10240 B
#define STAGE_B  (4 * TILE_B)          // Ah, Al, Bh, Bl
#define NSTAGE   3
#define SMEM_BYTES (NSTAGE * STAGE_B)  // 122880 B

__device__ __forceinline__ uint32_t smem_u32(const void* p) {
    uint32_t a;
    asm("{ .reg .u64 t; cvta.to.shared.u64 t, %1; cvt.u32.u64 %0, t; }"
        : "=r"(a) : "l"(p));
    return a;
}
__device__ __forceinline__ void cp_async16(uint32_t dst, const void* src) {
    asm volatile("cp.async.cg.shared.global [%0], [%1], 16;"
                 :: "r"(dst), "l"(src));
}
__device__ __forceinline__ void cp_commit() {
    asm volatile("cp.async.commit_group;" ::: "memory");
}
template<int N> __device__ __forceinline__ void cp_wait() {
    asm volatile("cp.async.wait_group %0;" :: "n"(N) : "memory");
}
__device__ __forceinline__ void ldsm4(uint32_t* r, uint32_t addr) {
    asm volatile("ldmatrix.sync.aligned.m8n8.x4.shared.b16 {%0,%1,%2,%3}, [%4];"
                 : "=r"(r[0]), "=r"(r[1]), "=r"(r[2]), "=r"(r[3]) : "r"(addr));
}
__device__ __forceinline__ void mma16816(float* c, const uint32_t* a,
                                         uint32_t b0, uint32_t b1) {
    asm volatile(
        "mma.sync.aligned.m16n8k16.row.col.f32.bf16.bf16.f32 "
        "{%0,%1,%2,%3}, {%4,%5,%6,%7}, {%8,%9}, {%0,%1,%2,%3};"
        : "+f"(c[0]), "+f"(c[1]), "+f"(c[2]), "+f"(c[3])
        : "r"(a[0]), "r"(a[1]), "r"(a[2]), "r"(a[3]), "r"(b0), "r"(b1));
}
__device__ __forceinline__ void split2(float x, float y, uint32_t& h, uint32_t& l) {
    __nv_bfloat162 hh = __floats2bfloat162_rn(x, y);
    float rx = x - __low2float(hh);
    float ry = y - __high2float(hh);
    __nv_bfloat162 ll = __floats2bfloat162_rn(rx, ry);
    h = *(uint32_t*)&hh; l = *(uint32_t*)&ll;
}

// ---------------------------------------------------------------------------
// Stage issue: cp.async one K-chunk (4 tiles of 128 rows x 64B) into st.
// ---------------------------------------------------------------------------
__device__ __forceinline__ void stage_issue(
    const bf16* __restrict__ Ah, const bf16* __restrict__ Al, size_t lda,
    const bf16* __restrict__ Bh, const bf16* __restrict__ Bl, size_t ldb,
    int m0, int n0, int kt, char* st, int tid)
{
    #pragma unroll
    for (int t = 0; t < 4; t++) {
        const bf16* base = (t == 0) ? Ah : (t == 1) ? Al : (t == 2) ? Bh : Bl;
        const size_t ld  = (t < 2) ? lda : ldb;
        const int    r0  = (t < 2) ? m0 : n0;
        #pragma unroll
        for (int j = 0; j < 2; j++) {
            int idx = j * 256 + tid;        // 0..511
            int row = idx >> 2;             // 0..127
            int seg = idx & 3;              // 16B segment
            const bf16* gp = base + (size_t)(r0 + row) * ld + kt + seg * 8;
            uint32_t dst = smem_u32(st + t * TILE_B + row * TROW + seg * 16);
            cp_async16(dst, gp);
        }
    }
}

// ---------------------------------------------------------------------------
// 128x128 GEMM: C[m,n] = scale * sum_k A[m,k]*B[n,k] (+bias), bf16 split inputs.
// Output: fp32 C if C != nullptr, else bf16 split (Ch, Cl).
// bias_mode: 0 none, 1 column bias[n], 2 row bias[m].
// 256 threads, 8 warps (wm 0..3 x wn 0..1), warp tile 32x64.
// ---------------------------------------------------------------------------
__device__ void gemm_mma(
    const bf16* __restrict__ Ah, const bf16* __restrict__ Al, size_t lda,
    const bf16* __restrict__ Bh, const bf16* __restrict__ Bl, size_t ldb,
    float* __restrict__ C, bf16* __restrict__ Ch, bf16* __restrict__ Cl,
    size_t ldc, const float* __restrict__ bias, int bias_mode, float scale,
    int m0, int n0, int nchunks)
{
    extern __shared__ __align__(128) char smem[];
    const int tid  = threadIdx.x;
    const int lane = tid & 31;
    const int wid  = tid >> 5;
    const int wm   = wid >> 1;
    const int wn   = wid & 1;

    float acc[2][8][4];
    #pragma unroll
    for (int i = 0; i < 2; i++)
        #pragma unroll
        for (int j = 0; j < 8; j++)
            #pragma unroll
            for (int q = 0; q < 4; q++) acc[i][j][q] = 0.f;

    const uint32_t a_off = (uint32_t)((wm * 32 + (lane & 15)) * TROW
                                      + ((lane >> 4) << 4));
    const uint32_t b_off = (uint32_t)((wn * 64 + (lane & 7) + ((lane >> 4) << 3)) * TROW
                                      + (((lane >> 3) & 1) << 4));

    // prologue: stages 0 and 1
    stage_issue(Ah, Al, lda, Bh, Bl, ldb, m0, n0, 0, smem, tid);
    cp_commit();
    if (nchunks > 1)
        stage_issue(Ah, Al, lda, Bh, Bl, ldb, m0, n0, 32, smem + STAGE_B, tid);
    cp_commit();

    int cur = 0, nxt2 = 2;                  // buffer indices: compute c, issue c+2
    for (int c = 0; c < nchunks; ++c) {
        cp_wait<1>();
        __syncthreads();

        if (c + 2 < nchunks)
            stage_issue(Ah, Al, lda, Bh, Bl, ldb, m0, n0, (c + 2) * 32,
                        smem + nxt2 * STAGE_B, tid);
        cp_commit();

        char* st = smem + cur * STAGE_B;
        const uint32_t hiA = smem_u32(st);
        const uint32_t loA = hiA + TILE_B;
        const uint32_t hiB = hiA + 2 * TILE_B;
        const uint32_t loB = hiA + 3 * TILE_B;

        #pragma unroll
        for (int s = 0; s < 2; s++) {
            const uint32_t KB = s * 32;
            uint32_t ah[2][4], al[2][4], bb[4][4];
            #pragma unroll
            for (int mt = 0; mt < 2; mt++)
                ldsm4(ah[mt], hiA + a_off + mt * 16 * TROW + KB);
            #pragma unroll
            for (int mt = 0; mt < 2; mt++)
                ldsm4(al[mt], loA + a_off + mt * 16 * TROW + KB);
            #pragma unroll
            for (int p = 0; p < 4; p++)
                ldsm4(bb[p], hiB + b_off + p * 16 * TROW + KB);
            #pragma unroll
            for (int mt = 0; mt < 2; mt++)
                #pragma unroll
                for (int p = 0; p < 4; p++) {
                    mma16816(acc[mt][2 * p],     ah[mt], bb[p][0], bb[p][1]);
                    mma16816(acc[mt][2 * p + 1], ah[mt], bb[p][2], bb[p][3]);
                    mma16816(acc[mt][2 * p],     al[mt], bb[p][0], bb[p][1]);
                    mma16816(acc[mt][2 * p + 1], al[mt], bb[p][2], bb[p][3]);
                }
            #pragma unroll
            for (int p = 0; p < 4; p++)
                ldsm4(bb[p], loB + b_off + p * 16 * TROW + KB);
            #pragma unroll
            for (int mt = 0; mt < 2; mt++)
                #pragma unroll
                for (int p = 0; p < 4; p++) {
                    mma16816(acc[mt][2 * p],     ah[mt], bb[p][0], bb[p][1]);
                    mma16816(acc[mt][2 * p + 1], ah[mt], bb[p][2], bb[p][3]);
                }
        }
        __syncthreads();
        cur  = (cur  == NSTAGE - 1) ? 0 : cur + 1;
        nxt2 = (nxt2 == NSTAGE - 1) ? 0 : nxt2 + 1;
    }

    // epilogue
    const int g   = lane >> 2;
    const int tig = lane & 3;
    #pragma unroll
    for (int mt = 0; mt < 2; mt++) {
        const int r0 = m0 + wm * 32 + mt * 16 + g;
        #pragma unroll
        for (int nt = 0; nt < 8; nt++) {
            const int col = n0 + wn * 64 + nt * 8 + tig * 2;
            float b0 = 0.f, b1 = 0.f;
            if (bias_mode == 1) { b0 = bias[col]; b1 = bias[col + 1]; }
            float v00 = acc[mt][nt][0] * scale + b0;
            float v01 = acc[mt][nt][1] * scale + b1;
            float v10 = acc[mt][nt][2] * scale + b0;
            float v11 = acc[mt][nt][3] * scale + b1;
            if (bias_mode == 2) {
                float rb0 = bias[r0], rb1 = bias[r0 + 8];
                v00 += rb0; v01 += rb0; v10 += rb1; v11 += rb1;
            }
            if (C) {
                *(float2*)(C + (size_t)r0 * ldc + col)       = make_float2(v00, v01);
                *(float2*)(C + (size_t)(r0 + 8) * ldc + col) = make_float2(v10, v11);
            } else {
                uint32_t h0, l0, h1, l1;
                split2(v00, v01, h0, l0);
                split2(v10, v11, h1, l1);
                *(uint32_t*)(Ch + (size_t)r0 * ldc + col)       = h0;
                *(uint32_t*)(Cl + (size_t)r0 * ldc + col)       = l0;
                *(uint32_t*)(Ch + (size_t)(r0 + 8) * ldc + col) = h1;
                *(uint32_t*)(Cl + (size_t)(r0 + 8) * ldc + col) = l1;
            }
        }
    }
}

// ---------------------------------------------------------------------------
// Prep: split xs and the 3 weight matrices into bf16 hi/lo.
// ---------------------------------------------------------------------------
__device__ __forceinline__ void cvt_arr(const float* __restrict__ in,
                                        bf16* __restrict__ hi,
                                        bf16* __restrict__ lo, size_t n4)
{
    const size_t t0 = blockIdx.x * blockDim.x + threadIdx.x;
    const size_t stride = (size_t)gridDim.x * blockDim.x;
    for (size_t i = t0; i < n4; i += stride) {
        float4 v = ((const float4*)in)[i];
        uint32_t h0, l0, h1, l1;
        split2(v.x, v.y, h0, l0);
        split2(v.z, v.w, h1, l1);
        ((uint2*)hi)[i] = make_uint2(h0, h1);
        ((uint2*)lo)[i] = make_uint2(l0, l1);
    }
}

__global__ __launch_bounds__(256) void prep_kernel(
    const float* __restrict__ xs, const float* __restrict__ wq,
    const float* __restrict__ wk, const float* __restrict__ wv)
{
    const size_t WN = (size_t)EDIM * HDIM;
    if      (blockIdx.y == 0) cvt_arr(xs, g_xh, g_xl, (size_t)MTOT * HDIM / 4);
    else if (blockIdx.y == 1) cvt_arr(wq, g_wh,          g_wl,          WN / 4);
    else if (blockIdx.y == 2) cvt_arr(wk, g_wh + WN,     g_wl + WN,     WN / 4);
    else                      cvt_arr(wv, g_wh + 2 * WN, g_wl + 2 * WN, WN / 4);
}

// ---------------------------------------------------------------------------
// GEMM wrappers
// ---------------------------------------------------------------------------
__global__ __launch_bounds__(256, 1)
void proj_qk_kernel(const float* __restrict__ bq, const float* __restrict__ bk)
{
    const size_t WN = (size_t)EDIM * HDIM;
    const int z = blockIdx.z;
    gemm_mma(g_xh, g_xl, HDIM,
             g_wh + z * WN, g_wl + z * WN, HDIM,
             nullptr, z ? g_kh : g_qh, z ? g_kl : g_ql, EDIM,
             z ? bk : bq, 1, 1.0f,
             blockIdx.y * 128, blockIdx.x * 128, HDIM / 32);
}

__global__ __launch_bounds__(256, 1)
void proj_vt_kernel(const float* __restrict__ bv)
{
    const size_t WN = (size_t)EDIM * HDIM;
    gemm_mma(g_wh + 2 * WN, g_wl + 2 * WN, HDIM,
             g_xh, g_xl, HDIM,
             nullptr, g_vth, g_vtl, MTOT,
             bv, 2, 1.0f,
             blockIdx.y * 128, blockIdx.x * 128, HDIM / 32);
}

__global__ __launch_bounds__(256, 1)
void qkt_kernel()
{
    if (blockIdx.x > blockIdx.y) return;       // above diagonal: never read
    const int b = blockIdx.z;
    gemm_mma(g_qh + (size_t)b * SEQ * EDIM, g_ql + (size_t)b * SEQ * EDIM, EDIM,
             g_kh + (size_t)b * SEQ * EDIM, g_kl + (size_t)b * SEQ * EDIM, EDIM,
             g_p + (size_t)b * SEQ * SEQ, nullptr, nullptr, SEQ,
             nullptr, 0, 0.03125f,
             blockIdx.y * 128, blockIdx.x * 128, EDIM / 32);
}

__global__ __launch_bounds__(256, 1)
void pv_kernel(float* __restrict__ out)
{
    const int b = blockIdx.z;
    const int nchunks = (blockIdx.y + 1) * 4;   // K bound = (y+1)*128
    gemm_mma(g_ph + (size_t)b * SEQ * SEQ, g_pl + (size_t)b * SEQ * SEQ, SEQ,
             g_vth + (size_t)b * SEQ, g_vtl + (size_t)b * SEQ, MTOT,
             out + (size_t)b * SEQ * EDIM, nullptr, nullptr, EDIM,
             nullptr, 0, 1.0f,
             blockIdx.y * 128, blockIdx.x * 128, nchunks);
}

// ---------------------------------------------------------------------------
// fp32 causal row softmax -> bf16 hi/lo P
// ---------------------------------------------------------------------------
__global__ __launch_bounds__(256) void softmax_kernel()
{
    const int m = blockIdx.x, b = blockIdx.y;
    const size_t roff = (size_t)b * SEQ * SEQ + (size_t)m * SEQ;
    const float* row = g_p + roff;
    const int nv = m + 1;
    const int tid = threadIdx.x;
    __shared__ float red[8];

    float mx = -3.4e38f;
    for (int n = tid; n < nv; n += 256) mx = fmaxf(mx, row[n]);
    #pragma unroll
    for (int o = 16; o; o >>= 1) mx = fmaxf(mx, __shfl_xor_sync(0xffffffffu, mx, o));
    if ((tid & 31) == 0) red[tid >> 5] = mx;
    __syncthreads();
    float mall = red[0];
    #pragma unroll
    for (int i = 1; i < 8; i++) mall = fmaxf(mall, red[i]);
    __syncthreads();

    float s = 0.f;
    for (int n = tid; n < nv; n += 256) s += __expf(row[n] - mall);
    #pragma unroll
    for (int o = 16; o; o >>= 1) s += __shfl_xor_sync(0xffffffffu, s, o);
    if ((tid & 31) == 0) red[tid >> 5] = s;
    __syncthreads();
    float tot = 0.f;
    #pragma unroll
    for (int i = 0; i < 8; i++) tot += red[i];
    const float inv = 1.0f / tot;

    bf16* ph = g_ph + roff;
    bf16* pl = g_pl + roff;
    for (int n2 = tid; n2 < SEQ / 2; n2 += 256) {
        const int n = n2 * 2;
        float p0 = (n     < nv) ? __expf(row[n]     - mall) * inv : 0.f;
        float p1 = (n + 1 < nv) ? __expf(row[n + 1] - mall) * inv : 0.f;
        uint32_t h, l;
        split2(p0, p1, h, l);
        *(uint32_t*)(ph + n) = h;
        *(uint32_t*)(pl + n) = l;
    }
}

// ---------------------------------------------------------------------------
extern "C" void kernel_launch(void* const* d_in, const int* in_sizes, int n_in,
                              void* d_out, int out_size)
{
    const float* xs   = (const float*)d_in[0];
    const float* WQ_w = (const float*)d_in[1];
    const float* WQ_b = (const float*)d_in[2];
    const float* WK_w = (const float*)d_in[3];
    const float* WK_b = (const float*)d_in[4];
    const float* WV_w = (const float*)d_in[5];
    const float* WV_b = (const float*)d_in[6];
    float* out = (float*)d_out;

    cudaFuncSetAttribute(proj_qk_kernel, cudaFuncAttributeMaxDynamicSharedMemorySize, SMEM_BYTES);
    cudaFuncSetAttribute(proj_vt_kernel, cudaFuncAttributeMaxDynamicSharedMemorySize, SMEM_BYTES);
    cudaFuncSetAttribute(qkt_kernel,     cudaFuncAttributeMaxDynamicSharedMemorySize, SMEM_BYTES);
    cudaFuncSetAttribute(pv_kernel,      cudaFuncAttributeMaxDynamicSharedMemorySize, SMEM_BYTES);

    prep_kernel<<<dim3(512, 4), 256>>>(xs, WQ_w, WK_w, WV_w);
    proj_qk_kernel<<<dim3(EDIM / 128, MTOT / 128, 2), 256, SMEM_BYTES>>>(WQ_b, WK_b);
    proj_vt_kernel<<<dim3(MTOT / 128, EDIM / 128, 1), 256, SMEM_BYTES>>>(WV_b);
    qkt_kernel<<<dim3(SEQ / 128, SEQ / 128, BATCH), 256, SMEM_BYTES>>>();
    softmax_kernel<<<dim3(SEQ, BATCH), 256>>>();
    pv_kernel<<<dim3(EDIM / 128, SEQ / 128, BATCH), 256, SMEM_BYTES>>>(out);
}